// round 8
// baseline (speedup 1.0000x reference)
#include <cuda_runtime.h>
#include <math.h>
#include <stdint.h>

#define NUM_CLASSES 1000000
#define DIMK 64
#define BATCHN 4096
#define NS 1024

// Scratch (device globals: allocation-free per harness rules)
__device__ float g_C[BATCHN * NS];     // logits (pre log_q subtraction): 16 MB
__device__ float g_ST[DIMK * NS];      // gathered sampled weights, d-major [64][1024]
__device__ float g_slq[NS];            // samp_log_q
__device__ float g_tlq[BATCHN];        // true_log_q

// ---------------------------------------------------------------------------
// Literal reconstruction of XLA:CPU's GenerateVF32Log (llvm_ir_runtime.cc),
// the routine jax-on-CPU uses for vectorized jnp.log(f32):
//   - Cephes constants, q1/q2 split ln2 (R7 proved the split is required)
//   - Estrin 3-chain combined via x^3
//   - VectorSupportLibrary::MulAdd == separate fmul + fadd, and jax disables
//     XLA CPU fast-math => NO fma contraction anywhere
//   - old-Eigen tail order: x = (x - 0.5*x2) + y, then + e*q2
// __fmul_rn/__fadd_rn block nvcc's own -fmad contraction.
// Valid for normal positive x (our args are >= 1).
// ---------------------------------------------------------------------------
__device__ __forceinline__ float xla_logf(float xx) {
    uint32_t ib = __float_as_uint(xx);
    float e = __fadd_rn((float)((int)(ib >> 23) - 0x7f), 1.0f);
    float x = __uint_as_float((ib & 0x007fffffu) | 0x3f000000u);  // [0.5, 1)
    bool mask = x < 0.707106781186547524f;
    float tmp = mask ? x : 0.0f;
    x = __fadd_rn(x, -1.0f);
    e = __fadd_rn(e, mask ? -1.0f : 0.0f);
    x = __fadd_rn(x, tmp);

    float x2 = __fmul_rn(x, x);
    float x3 = __fmul_rn(x2, x);

    // Estrin 3-chain, all MulAdds UNFUSED (mul then add)
    float y  = __fadd_rn(__fmul_rn(7.0376836292E-2f, x), -1.1514610310E-1f);
    float y1 = __fadd_rn(__fmul_rn(-1.2420140846E-1f, x), 1.4249322787E-1f);
    float y2 = __fadd_rn(__fmul_rn(2.0000714765E-1f, x), -2.4999993993E-1f);
    y  = __fadd_rn(__fmul_rn(y, x), 1.1676998740E-1f);
    y1 = __fadd_rn(__fmul_rn(y1, x), -1.6668057665E-1f);
    y2 = __fadd_rn(__fmul_rn(y2, x), 3.3333331174E-1f);
    y  = __fadd_rn(__fmul_rn(y, x3), y1);
    y  = __fadd_rn(__fmul_rn(y, x3), y2);
    y  = __fmul_rn(y, x3);

    // Tail: q1/q2 split, old-Eigen association
    float t1 = __fmul_rn(e, -2.12194440e-4f);   // e*q1
    float t2 = __fmul_rn(x2, 0.5f);             // 0.5*x2
    y = __fadd_rn(y, t1);                        // y += e*q1
    x = __fadd_rn(x, -t2);                       // x -= 0.5*x2
    float t3 = __fmul_rn(e, 0.693359375f);       // e*q2
    x = __fadd_rn(x, y);                         // x += y
    x = __fadd_rn(x, t3);                        // x += e*q2
    return x;
}

// Reference: P = (log(c+2) - log(c+1)) / log(NC+1); q = log(1024 * P),
// all logs f32 via the XLA log; adds/sub/div/mul IEEE f32.
__device__ __forceinline__ float log_q_of(int c) {
    float cf = (float)c;                    // exact: c < 2^24
    float l2 = xla_logf(__fadd_rn(cf, 2.0f));
    float l1 = xla_logf(__fadd_rn(cf, 1.0f));
    float lnc = xla_logf(1000001.0f);
    float p = __fdiv_rn(__fadd_rn(l2, -l1), lnc);
    float np = __fmul_rn(1024.0f, p);       // exact power-of-two scale
    return xla_logf(np);
}

// K1: gather sampled weight columns into d-major layout + precompute log-q's.
__global__ void __launch_bounds__(256) gather_kernel(
    const float* __restrict__ item,
    const int*   __restrict__ labels,
    const int*   __restrict__ sid)
{
    int idx = blockIdx.x * 256 + threadIdx.x;       // 0 .. 65535
    int d = idx >> 10;
    int j = idx & 1023;
    int c = sid[j];
    g_ST[idx] = item[(size_t)d * NUM_CLASSES + (size_t)c];
    if (idx < NS)     g_slq[idx] = log_q_of(sid[idx]);
    if (idx < BATCHN) g_tlq[idx] = log_q_of(labels[idx]);
}

// K2: C[b][j] = sum_d U[d][b] * ST[d][j].  BM=128, BN=128, BK=32 (x2).
__global__ void __launch_bounds__(256) gemm_kernel(const float* __restrict__ U)
{
    __shared__ float Us[32][128];
    __shared__ float Ss[32][128];

    int b0 = blockIdx.x * 128;
    int j0 = blockIdx.y * 128;
    int tid = (int)threadIdx.x;
    int tx = tid & 15;        // 16 col-threads
    int ty = tid >> 4;        // 16 row-threads

    float acc[8][8];
    #pragma unroll
    for (int i = 0; i < 8; i++)
        #pragma unroll
        for (int j = 0; j < 8; j++) acc[i][j] = 0.0f;

    #pragma unroll
    for (int k0 = 0; k0 < DIMK; k0 += 32) {
        #pragma unroll
        for (int t = 0; t < 4; t++) {
            int u  = tid + t * 256;       // 0..1023
            int d  = u >> 5;              // 0..31
            int x4 = (u & 31) << 2;       // 0..124
            *(float4*)&Us[d][x4] = *(const float4*)&U[(size_t)(k0 + d) * BATCHN + b0 + x4];
            *(float4*)&Ss[d][x4] = *(const float4*)&g_ST[(k0 + d) * NS + j0 + x4];
        }
        __syncthreads();

        #pragma unroll
        for (int d = 0; d < 32; d++) {
            float a[8], bb[8];
            #pragma unroll
            for (int i = 0; i < 8; i++) a[i]  = Us[d][ty * 8 + i];
            #pragma unroll
            for (int j = 0; j < 8; j++) bb[j] = Ss[d][tx * 8 + j];
            #pragma unroll
            for (int i = 0; i < 8; i++)
                #pragma unroll
                for (int j = 0; j < 8; j++)
                    acc[i][j] = fmaf(a[i], bb[j], acc[i][j]);
        }
        __syncthreads();
    }

    #pragma unroll
    for (int i = 0; i < 8; i++) {
        float* dst = &g_C[(size_t)(b0 + ty * 8 + i) * NS + j0 + tx * 8];
        float4 v0 = make_float4(acc[i][0], acc[i][1], acc[i][2], acc[i][3]);
        float4 v1 = make_float4(acc[i][4], acc[i][5], acc[i][6], acc[i][7]);
        *(float4*)(dst)     = v0;
        *(float4*)(dst + 4) = v1;
    }
}

// K3: fused true-logit gather + mask + softmax + loss. One warp per batch row.
__global__ void __launch_bounds__(256) softmax_kernel(
    const float* __restrict__ U,
    const float* __restrict__ item,
    const int*   __restrict__ labels,
    const int*   __restrict__ sid,
    float*       __restrict__ out)
{
    __shared__ float s_slq[NS];
    __shared__ int   s_sid[NS];

    int tid = (int)threadIdx.x;
    for (int t = tid; t < NS; t += 256) {
        s_slq[t] = g_slq[t];
        s_sid[t] = sid[t];
    }
    __syncthreads();

    int lane = tid & 31;
    int b = blockIdx.x * 8 + (tid >> 5);
    int lab = labels[b];

    // True logit: dot(U[:,b], item[:,lab]) - true_log_q[b]
    float td = U[(size_t)lane * BATCHN + b]        * item[(size_t)lane        * NUM_CLASSES + lab]
             + U[(size_t)(lane + 32) * BATCHN + b] * item[(size_t)(lane + 32) * NUM_CLASSES + lab];
    #pragma unroll
    for (int o = 16; o; o >>= 1) td += __shfl_xor_sync(0xffffffffu, td, o);
    float true_logit = td - g_tlq[b];

    const float* Crow = &g_C[(size_t)b * NS];
    float l[32];
    float m = true_logit;
    #pragma unroll
    for (int k = 0; k < 32; k++) {
        int j = lane + (k << 5);
        float v = Crow[j] - s_slq[j];
        if (s_sid[j] == lab) v -= 1000000000.0f;
        l[k] = v;
        m = fmaxf(m, v);
    }
    #pragma unroll
    for (int o = 16; o; o >>= 1) m = fmaxf(m, __shfl_xor_sync(0xffffffffu, m, o));

    float s = 0.0f;
    #pragma unroll
    for (int k = 0; k < 32; k++) s += __expf(l[k] - m);
    #pragma unroll
    for (int o = 16; o; o >>= 1) s += __shfl_xor_sync(0xffffffffu, s, o);
    s += __expf(true_logit - m);

    if (lane == 0) out[b] = m + xla_logf(s) - true_logit;
}

extern "C" void kernel_launch(void* const* d_in, const int* in_sizes, int n_in,
                              void* d_out, int out_size)
{
    const float* item = (const float*)d_in[0];   // [64, 1000000]
    const float* user = (const float*)d_in[1];   // [64, 4096]
    const int*   lab  = (const int*)  d_in[2];   // [4096, 1]
    const int*   sid  = (const int*)  d_in[3];   // [1024]
    float*       out  = (float*)d_out;           // [4096, 1]

    gather_kernel<<<256, 256>>>(item, lab, sid);
    gemm_kernel<<<dim3(32, 8), 256>>>(user);
    softmax_kernel<<<512, 256>>>(user, item, lab, sid, out);
}